// round 7
// baseline (speedup 1.0000x reference)
#include <cuda_runtime.h>
#include <cstdint>

typedef unsigned long long ull;

// Rank-16 factors with parity compaction:
//   psi[i*4096 + j] = sum_{m=0..7} Lt[i][m] * R[(i&1)*8 + m][j]
__device__ __align__(16) float gLt[4096 * 8];    // [i][m]
__device__ __align__(16) float gR [16 * 4096];   // [p*8+m][j]

// Gate id schedules per side, ordered by layer then wire.
// e:        0  1  2  3  4  5   6  7  8  9 10   11 12 13 14 15 16   17 18 19 20 21
// b1=10-u: 10  8  6  4  2  0   9  7  5  3  1   10  8  6  4  2  0    9  7  5  3  1
__constant__ short c_Lgi[22] = { 0, 1, 2, 3, 4, 5,  12,13,14,15,16,  23,24,25,26,27,28,  35,36,37,38,39 };
__constant__ short c_Rgi[22] = { 6, 7, 8, 9,10,11,  18,19,20,21,22,  29,30,31,32,33,34,  41,42,43,44,45 };

// Bank-conflict-killing smem swizzle: float-index bits 3,4 ^= bits 7,8.
__device__ __forceinline__ int swz(int i) { return i ^ (((i >> 7) & 3) << 3); }

// ---- packed f32x2 helpers ----
__device__ __forceinline__ ull f2pack(float a, float b) {
    ull r; asm("mov.b64 %0,{%1,%2};" : "=l"(r) : "f"(a), "f"(b)); return r;
}
__device__ __forceinline__ void f2unpack(ull x, float& a, float& b) {
    asm("mov.b64 {%0,%1},%2;" : "=f"(a), "=f"(b) : "l"(x));
}
__device__ __forceinline__ ull f2mul(ull a, ull b) {
    ull r; asm("mul.rn.f32x2 %0,%1,%2;" : "=l"(r) : "l"(a), "l"(b)); return r;
}
__device__ __forceinline__ ull f2fma(ull a, ull b, ull c) {
    ull r; asm("fma.rn.f32x2 %0,%1,%2,%3;" : "=l"(r) : "l"(a), "l"(b), "l"(c)); return r;
}

// Packed 2q butterfly; coefficient roles identical to the scalar version:
//  a' = g0 a + g2 b + g8  c + g10 d   (a=x00, b=i1-toggle, c=i0-toggle, d=both)
__device__ __forceinline__ void bfly2(ull& A, ull& B, ull& C, ull& D, const ull* g) {
    ull x00 = A, x01 = B, x10 = C, x11 = D, t;
    t = f2mul(g[0], x00); t = f2fma(g[2], x01, t); t = f2fma(g[ 8], x10, t); A = f2fma(g[10], x11, t);
    t = f2mul(g[1], x00); t = f2fma(g[3], x01, t); t = f2fma(g[ 9], x10, t); B = f2fma(g[11], x11, t);
    t = f2mul(g[4], x00); t = f2fma(g[6], x01, t); t = f2fma(g[12], x10, t); C = f2fma(g[14], x11, t);
    t = f2mul(g[5], x00); t = f2fma(g[7], x01, t); t = f2fma(g[13], x10, t); D = f2fma(g[15], x11, t);
}
// packed 1q pair: y0' = m0 y0 + m1 y1 ; y1' = m2 y0 + m3 y1
__device__ __forceinline__ void op1p(ull& Y0, ull& Y1, const ull* m) {
    ull y0 = Y0, y1 = Y1, t;
    t = f2mul(m[0], y0); Y0 = f2fma(m[1], y1, t);
    t = f2mul(m[2], y0); Y1 = f2fma(m[3], y1, t);
}

// Packings of the 16-amp tile v[i3 i2 i1 i0]:
//   u[k] = {v[2k], v[2k+1]}   (bit0 packed; u-index bits = v bits 1..3)
//   w[k] = {v[k],  v[k|8]}    (bit3 packed; w-index bits = v bits 0..2)
__device__ __forceinline__ void pack_u(const float* v, ull* u) {
#pragma unroll
    for (int k = 0; k < 8; ++k) u[k] = f2pack(v[2*k], v[2*k+1]);
}
__device__ __forceinline__ void u_to_w(const ull* u, ull* w) {
    float a[16];
#pragma unroll
    for (int k = 0; k < 8; ++k) f2unpack(u[k], a[2*k], a[2*k+1]);
#pragma unroll
    for (int k = 0; k < 8; ++k) w[k] = f2pack(a[k], a[k|8]);
}
__device__ __forceinline__ void unpack_w(const ull* w, float* v) {
#pragma unroll
    for (int k = 0; k < 8; ++k) f2unpack(w[k], v[k], v[k|8]);
}

// gate bits (2,3) on u-packing: groups (u[s], u[s|2], u[s|4], u[s|6]), s=0,1
__device__ __forceinline__ void high_u(ull* u, const ull* g) {
    bfly2(u[0], u[2], u[4], u[6], g);
    bfly2(u[1], u[3], u[5], u[7], g);
}
// gate bits (0,1) on w-packing: groups (w[s], w[s|1], w[s|2], w[s|3]), s=0,4
__device__ __forceinline__ void low_w(ull* w, const ull* g) {
    bfly2(w[0], w[1], w[2], w[3], g);
    bfly2(w[4], w[5], w[6], w[7], g);
}
// gate bits (1,2) on w-packing: groups (w[s], w[s|2], w[s|4], w[s|6]), s=0,1
__device__ __forceinline__ void mid_w(ull* w, const ull* g) {
    bfly2(w[0], w[2], w[4], w[6], g);
    bfly2(w[1], w[3], w[5], w[7], g);
}
// 1q on v-bit3 in u-packing: pairs (u[k], u[k|4]), k=0..3
__device__ __forceinline__ void op1_b3_u(ull* u, const ull* m) {
#pragma unroll
    for (int k = 0; k < 4; ++k) op1p(u[k], u[k|4], m);
}
// 1q on v-bit0 in w-packing: pairs (w[k], w[k|1]), k even
__device__ __forceinline__ void op1_b0_w(ull* w, const ull* m) {
#pragma unroll
    for (int k = 0; k < 8; k += 2) op1p(w[k], w[k+1], m);
}

__device__ __forceinline__ void load_gatep(ull* gp, const ull* gsp) {
#pragma unroll
    for (int c = 0; c < 8; ++c) {
        ulonglong2 t = ((const ulonglong2*)gsp)[c];
        gp[2*c] = t.x; gp[2*c+1] = t.y;
    }
}

// ---- tile exchange through swizzled smem; tile bits T0..T0+3 ----
template<int T0>
__device__ __forceinline__ void store_tile(float* sv, const float* v, int tid) {
    if constexpr (T0 == 0) {
        const int base = tid << 4;
#pragma unroll
        for (int c = 0; c < 4; ++c)
            *(float4*)&sv[swz(base + c*4)] = make_float4(v[4*c], v[4*c+1], v[4*c+2], v[4*c+3]);
    } else {
        const int base = ((tid >> T0) << (T0 + 4)) | (tid & ((1 << T0) - 1));
#pragma unroll
        for (int k = 0; k < 16; ++k) sv[swz(base + (k << T0))] = v[k];
    }
}
template<int T0>
__device__ __forceinline__ void load_tile(const float* sv, float* v, int tid) {
    if constexpr (T0 == 0) {
        const int base = tid << 4;
#pragma unroll
        for (int c = 0; c < 4; ++c) {
            float4 t = *(const float4*)&sv[swz(base + c*4)];
            v[4*c] = t.x; v[4*c+1] = t.y; v[4*c+2] = t.z; v[4*c+3] = t.w;
        }
    } else {
        const int base = ((tid >> T0) << (T0 + 4)) | (tid & ((1 << T0) - 1));
#pragma unroll
        for (int k = 0; k < 16; ++k) v[k] = sv[swz(base + (k << T0))];
    }
}

// 32 blocks: 0..15 -> L_{ab} (k=a*4+b), 16..31 -> R_{ab}. 256 threads, 16 amps each.
// (unchanged from the passing R6 kernel)
__global__ void __launch_bounds__(256) k_smallsim(const float* __restrict__ states,
                                                  const float* __restrict__ gates)
{
    __shared__ __align__(16) float sv[4096];
    __shared__ __align__(16) ull gshp[352];    // packed {g,g} coefficients, 22 gates
    __shared__ float st[24];

    const int tid  = threadIdx.x;
    const int blk  = blockIdx.x;
    const int side = blk >> 4;
    const int k    = blk & 15;
    const int a    = k >> 2;
    const int b    = k & 3;

#pragma unroll
    for (int t = tid; t < 352; t += 256) {
        int e = t >> 4;
        int gi = side ? c_Rgi[e] : c_Lgi[e];
        float val = gates[gi * 16 + (t & 15)];
        gshp[t] = f2pack(val, val);
    }
    if (tid >= 232) st[tid - 232] = states[(side ? 24 : 0) + tid - 232];

    // crossing-gate single-qubit factors, layout m[o*2+i], packed {m,m}
    ull mp1[4], mp2[4];
    {
        float m1[4], m2[4];
        if (side == 0) {
            m1[0]=m1[1]=m1[2]=m1[3]=0.f;  m1[(a & 1)*2 + (a >> 1)] = 1.f;   // P_a on bit 0
            m2[0]=m2[1]=m2[2]=m2[3]=0.f;  m2[(b & 1)*2 + (b >> 1)] = 1.f;   // P'_b on bit 0
        } else {
            const float* g17 = gates + 17*16 + (a >> 1)*8 + (a & 1)*4;       // Q_a on bit 11
            m1[0]=g17[0]; m1[1]=g17[2]; m1[2]=g17[1]; m1[3]=g17[3];
            const float* g40 = gates + 40*16 + (b >> 1)*8 + (b & 1)*4;       // Q'_b on bit 11
            m2[0]=g40[0]; m2[1]=g40[2]; m2[2]=g40[1]; m2[3]=g40[3];
        }
#pragma unroll
        for (int j = 0; j < 4; ++j) { mp1[j] = f2pack(m1[j], m1[j]); mp2[j] = f2pack(m2[j], m2[j]); }
    }
    __syncthreads();

    float v[16];
    ull   u[8], w[8], gp[16], gq[16];

    // Init directly into P1's tile (bits 8..11 local; bits 0..7 = tid).
    {
        float pb = 1.f;
#pragma unroll
        for (int wv = 4; wv < 12; ++wv) pb *= st[2*wv + ((tid >> (11 - wv)) & 1)];
#pragma unroll
        for (int kk = 0; kk < 16; ++kk) {
            float p = pb;
#pragma unroll
            for (int wv = 0; wv < 4; ++wv) p *= st[2*wv + ((kk >> (3 - wv)) & 1)];
            v[kk] = p;
        }
    }

    // P1: tile 8-11 — e0 high, e1 low; right: Q_a on bit 11 (commutes past low: bits {3} vs {0,1})
    pack_u(v, u);
    load_gatep(gp, gshp + 0*16); load_gatep(gq, gshp + 1*16);
    high_u(u, gp);
    if (side) op1_b3_u(u, mp1);
    u_to_w(u, w); low_w(w, gq);
    unpack_w(w, v);
    store_tile<8>(sv, v, tid); __syncthreads();

    // P2: tile 4-7 — e2 high, e3 low
    load_tile<4>(sv, v, tid);  pack_u(v, u);
    load_gatep(gp, gshp + 2*16); load_gatep(gq, gshp + 3*16);
    high_u(u, gp); u_to_w(u, w); low_w(w, gq);
    unpack_w(w, v); store_tile<4>(sv, v, tid); __syncthreads();

    // P3: tile 0-3 — e4 high, e5 low, e10 mid; left: P_a on bit 0
    load_tile<0>(sv, v, tid);  pack_u(v, u);
    load_gatep(gp, gshp + 4*16); load_gatep(gq, gshp + 5*16);
    high_u(u, gp); u_to_w(u, w); low_w(w, gq);
    load_gatep(gp, gshp + 10*16); mid_w(w, gp);
    if (!side) op1_b0_w(w, mp1);
    unpack_w(w, v); store_tile<0>(sv, v, tid); __syncthreads();

    // P4: tile 7-10 — e6 high, e7 low
    load_tile<7>(sv, v, tid);  pack_u(v, u);
    load_gatep(gp, gshp + 6*16); load_gatep(gq, gshp + 7*16);
    high_u(u, gp); u_to_w(u, w); low_w(w, gq);
    unpack_w(w, v); store_tile<7>(sv, v, tid); __syncthreads();

    // P5: tile 3-6 — e8 high, e9 low
    load_tile<3>(sv, v, tid);  pack_u(v, u);
    load_gatep(gp, gshp + 8*16); load_gatep(gq, gshp + 9*16);
    high_u(u, gp); u_to_w(u, w); low_w(w, gq);
    unpack_w(w, v); store_tile<3>(sv, v, tid); __syncthreads();

    // P6: tile 8-11 — e11 high, e12 low; right: Q'_b on bit 11 (commutes with e12..e16)
    load_tile<8>(sv, v, tid);  pack_u(v, u);
    load_gatep(gp, gshp + 11*16); load_gatep(gq, gshp + 12*16);
    high_u(u, gp);
    if (side) op1_b3_u(u, mp2);
    u_to_w(u, w); low_w(w, gq);
    unpack_w(w, v); store_tile<8>(sv, v, tid); __syncthreads();

    // P7: tile 4-7 — e13 high, e14 low
    load_tile<4>(sv, v, tid);  pack_u(v, u);
    load_gatep(gp, gshp + 13*16); load_gatep(gq, gshp + 14*16);
    high_u(u, gp); u_to_w(u, w); low_w(w, gq);
    unpack_w(w, v); store_tile<4>(sv, v, tid); __syncthreads();

    // P8: tile 0-3 — e15 high, e16 low, e21 mid; left: P'_b on bit 0
    load_tile<0>(sv, v, tid);  pack_u(v, u);
    load_gatep(gp, gshp + 15*16); load_gatep(gq, gshp + 16*16);
    high_u(u, gp); u_to_w(u, w); low_w(w, gq);
    load_gatep(gp, gshp + 21*16); mid_w(w, gp);
    if (!side) op1_b0_w(w, mp2);
    unpack_w(w, v); store_tile<0>(sv, v, tid); __syncthreads();

    // P9: tile 7-10 — e17 high, e18 low
    load_tile<7>(sv, v, tid);  pack_u(v, u);
    load_gatep(gp, gshp + 17*16); load_gatep(gq, gshp + 18*16);
    high_u(u, gp); u_to_w(u, w); low_w(w, gq);
    unpack_w(w, v); store_tile<7>(sv, v, tid); __syncthreads();

    // P10: tile 3-6 — e19 high, e20 low
    load_tile<3>(sv, v, tid);  pack_u(v, u);
    load_gatep(gp, gshp + 19*16); load_gatep(gq, gshp + 20*16);
    high_u(u, gp); u_to_w(u, w); low_w(w, gq);
    unpack_w(w, v); store_tile<3>(sv, v, tid); __syncthreads();

    // Final global stores (read through the swizzle).
    const int mm = a * 2 + (b >> 1);
    const int p  = b & 1;
    if (side == 0) {
#pragma unroll
        for (int t = tid; t < 2048; t += 256) {
            int i = 2 * t + p;
            gLt[i * 8 + mm] = sv[swz(i)];
        }
    } else {
#pragma unroll
        for (int j = tid; j < 4096; j += 256)
            gR[(p * 8 + mm) * 4096 + j] = sv[swz(j)];
    }
}

// One ib-tile of the parity-specialized rank-8 expansion, TWO float4 columns per
// thread (jq0 and jq0+128). Each L broadcast element now feeds 8 FMAs (was 4),
// halving LDS instruction count and L1 broadcast traffic per unit output.
__device__ __forceinline__ void expand_tile2(
    const ull* sLbuf,
    const ull* r0lo, const ull* r0hi, const ull* r1lo, const ull* r1hi,
    float4* __restrict__ out, int ib, int jq0, int par)
{
    const ulonglong2* sL2 = reinterpret_cast<const ulonglong2*>(sLbuf);
#pragma unroll 4
    for (int rr = 0; rr < 16; rr += 2) {
        const int ra = 2 * rr + par;
        const int rb = ra + 2;
        ull A0 = 0ull, A1 = 0ull, B0 = 0ull, B1 = 0ull;   // col0: rows ra, rb
        ull C0 = 0ull, C1 = 0ull, D0 = 0ull, D1 = 0ull;   // col1: rows ra, rb
#pragma unroll
        for (int mq = 0; mq < 4; ++mq) {
            ulonglong2 lA = sL2[ra * 4 + mq];
            ulonglong2 lB = sL2[rb * 4 + mq];
            asm("fma.rn.f32x2 %0, %1, %2, %0;" : "+l"(A0) : "l"(lA.x), "l"(r0lo[2*mq]));
            asm("fma.rn.f32x2 %0, %1, %2, %0;" : "+l"(A1) : "l"(lA.x), "l"(r0hi[2*mq]));
            asm("fma.rn.f32x2 %0, %1, %2, %0;" : "+l"(C0) : "l"(lA.x), "l"(r1lo[2*mq]));
            asm("fma.rn.f32x2 %0, %1, %2, %0;" : "+l"(C1) : "l"(lA.x), "l"(r1hi[2*mq]));
            asm("fma.rn.f32x2 %0, %1, %2, %0;" : "+l"(B0) : "l"(lB.x), "l"(r0lo[2*mq]));
            asm("fma.rn.f32x2 %0, %1, %2, %0;" : "+l"(B1) : "l"(lB.x), "l"(r0hi[2*mq]));
            asm("fma.rn.f32x2 %0, %1, %2, %0;" : "+l"(D0) : "l"(lB.x), "l"(r1lo[2*mq]));
            asm("fma.rn.f32x2 %0, %1, %2, %0;" : "+l"(D1) : "l"(lB.x), "l"(r1hi[2*mq]));
            asm("fma.rn.f32x2 %0, %1, %2, %0;" : "+l"(A0) : "l"(lA.y), "l"(r0lo[2*mq+1]));
            asm("fma.rn.f32x2 %0, %1, %2, %0;" : "+l"(A1) : "l"(lA.y), "l"(r0hi[2*mq+1]));
            asm("fma.rn.f32x2 %0, %1, %2, %0;" : "+l"(C0) : "l"(lA.y), "l"(r1lo[2*mq+1]));
            asm("fma.rn.f32x2 %0, %1, %2, %0;" : "+l"(C1) : "l"(lA.y), "l"(r1hi[2*mq+1]));
            asm("fma.rn.f32x2 %0, %1, %2, %0;" : "+l"(B0) : "l"(lB.y), "l"(r0lo[2*mq+1]));
            asm("fma.rn.f32x2 %0, %1, %2, %0;" : "+l"(B1) : "l"(lB.y), "l"(r0hi[2*mq+1]));
            asm("fma.rn.f32x2 %0, %1, %2, %0;" : "+l"(D0) : "l"(lB.y), "l"(r1lo[2*mq+1]));
            asm("fma.rn.f32x2 %0, %1, %2, %0;" : "+l"(D1) : "l"(lB.y), "l"(r1hi[2*mq+1]));
        }
        float x0, x1, x2, x3;
        f2unpack(A0, x0, x1); f2unpack(A1, x2, x3);
        out[(ib * 32 + ra) * 1024 + jq0]       = make_float4(x0, x1, x2, x3);
        f2unpack(C0, x0, x1); f2unpack(C1, x2, x3);
        out[(ib * 32 + ra) * 1024 + jq0 + 128] = make_float4(x0, x1, x2, x3);
        f2unpack(B0, x0, x1); f2unpack(B1, x2, x3);
        out[(ib * 32 + rb) * 1024 + jq0]       = make_float4(x0, x1, x2, x3);
        f2unpack(D0, x0, x1); f2unpack(D1, x2, x3);
        out[(ib * 32 + rb) * 1024 + jq0 + 128] = make_float4(x0, x1, x2, x3);
    }
}

// Grid (4, 64), block 256. Thread = (col 0..127, par), owns float4 columns
// jq0 = jb*256+col and jq0+128. R regs reused across 2 ib-tiles.
__global__ void __launch_bounds__(256, 2) k_expand(float4* __restrict__ out)
{
    __shared__ __align__(16) ull sLd[2][256];

    const int tid = threadIdx.x;
    const int col = tid & 127;
    const int par = tid >> 7;
    const int jb  = blockIdx.x;     // 0..3
    const int by  = blockIdx.y;     // 0..63 -> ib = 2*by, 2*by+1
    const int jq0 = jb * 256 + col;

    // L tile 0 into smem; prefetch tile 1 into a register.
    float l0 = gLt[(2*by + 0) * 256 + tid];
    float l1 = gLt[(2*by + 1) * 256 + tid];
    sLd[0][tid] = f2pack(l0, l0);

    // R preload: this thread's parity slice for BOTH columns (reused across tiles).
    const float4* gR4 = reinterpret_cast<const float4*>(gR);
    ull r0lo[8], r0hi[8], r1lo[8], r1hi[8];
#pragma unroll
    for (int m = 0; m < 8; ++m) {
        float4 r = gR4[(par * 8 + m) * 1024 + jq0];
        r0lo[m] = f2pack(r.x, r.y);
        r0hi[m] = f2pack(r.z, r.w);
        float4 s = gR4[(par * 8 + m) * 1024 + jq0 + 128];
        r1lo[m] = f2pack(s.x, s.y);
        r1hi[m] = f2pack(s.z, s.w);
    }
    __syncthreads();

    expand_tile2(sLd[0], r0lo, r0hi, r1lo, r1hi, out, 2*by + 0, jq0, par);

    sLd[1][tid] = f2pack(l1, l1);   // disjoint from sLd[0] reads: no pre-bar needed
    __syncthreads();

    expand_tile2(sLd[1], r0lo, r0hi, r1lo, r1hi, out, 2*by + 1, jq0, par);
}

extern "C" void kernel_launch(void* const* d_in, const int* in_sizes, int n_in,
                              void* d_out, int out_size)
{
    const float* states = (const float*)d_in[0];   // (24, 2) f32
    const float* gates  = (const float*)d_in[1];   // (46, 2,2,2,2) f32
    (void)in_sizes; (void)n_in; (void)out_size;

    k_smallsim<<<32, 256>>>(states, gates);
    k_expand<<<dim3(4, 64), 256>>>((float4*)d_out);
}